// round 2
// baseline (speedup 1.0000x reference)
#include <cuda_runtime.h>

typedef unsigned long long ull;

#define NB    256
#define NT    512
#define NIN   64
#define NH    128
#define NG3   384

// ---------------- static scratch (no runtime allocation) ----------------
__device__ float g_gx[(size_t)NB * NT * NG3];    // 201 MB: per-layer input projections
__device__ float g_hseq[(size_t)NB * NT * NH];   // 67 MB: per-layer hidden sequence
__device__ ull   g_wpk[64 * NG3];                // k-pair-packed W_ih

// ---------------- f32x2 helpers ----------------
__device__ __forceinline__ ull ffma2(ull a, ull b, ull c) {
    ull d;
    asm("fma.rn.f32x2 %0, %1, %2, %3;" : "=l"(d) : "l"(a), "l"(b), "l"(c));
    return d;
}
__device__ __forceinline__ float f32x2_sum(ull a) {
    float lo, hi;
    asm("mov.b64 {%0, %1}, %2;" : "=f"(lo), "=f"(hi) : "l"(a));
    return lo + hi;
}
__device__ __forceinline__ ull pack2(float lo, float hi) {
    ull u;
    asm("mov.b64 %0, {%1, %2};" : "=l"(u) : "f"(lo), "f"(hi));
    return u;
}
__device__ __forceinline__ float sigf(float x) { return 1.0f / (1.0f + __expf(-x)); }

// ---------------- pack W_ih [384,K] row-major -> wpk[i][n] (i = k-pair) ----------------
__global__ void pack_wih_kernel(const float* __restrict__ w, int HK) {
    int idx = blockIdx.x * blockDim.x + threadIdx.x;
    if (idx >= HK * NG3) return;
    int n = idx % NG3;
    int i = idx / NG3;
    float2 v = *reinterpret_cast<const float2*>(w + (size_t)n * (2 * HK) + 2 * i);
    g_wpk[(size_t)i * NG3 + n] = pack2(v.x, v.y);
}

// ---------------- gx GEMM: g_gx[m,384] = A[m,K] @ W^T + b_ih ----------------
// CTA tile 128x128, 256 threads, 8x8 thread tile, f32x2 over k-pairs, whole K in smem.
template <int K>
__global__ __launch_bounds__(256, 1)
void gemm_gx_kernel(const float* __restrict__ A, const float* __restrict__ bih) {
    constexpr int HK  = K / 2;
    constexpr int LDA = HK + 2;              // even -> float4 stores stay 16B aligned
    extern __shared__ ull sm[];
    ull* As = sm;                            // [128][LDA]
    ull* Ws = sm + 128 * LDA;                // [HK][128]

    int tid = threadIdx.x;
    int mb = blockIdx.x, nb = blockIdx.y;

    // A tile: coalesced float4 global loads, natural [m][k-pair] ull layout
    {
        const float4* Ag = reinterpret_cast<const float4*>(A + (size_t)mb * 128 * K);
        float4* Asf = reinterpret_cast<float4*>(As);
        #pragma unroll
        for (int p = 0; p < (128 * K / 4) / 256; ++p) {
            int idx = tid + p * 256;
            int m = idx / (K / 4);
            int q = idx % (K / 4);
            Asf[m * (LDA / 2) + q] = Ag[(size_t)m * (K / 4) + q];
        }
    }
    // W tile from pre-packed global
    {
        #pragma unroll
        for (int p = 0; p < (HK * 128) / 256; ++p) {
            int idx = tid + p * 256;
            int i = idx >> 7, n = idx & 127;
            Ws[i * 128 + n] = g_wpk[(size_t)i * NG3 + nb * 128 + n];
        }
    }
    __syncthreads();

    int ty = tid >> 4, tx = tid & 15;        // m-group / n-group (n interleaved stride 16)
    ull acc[8][8];
    #pragma unroll
    for (int r = 0; r < 8; ++r)
        #pragma unroll
        for (int c = 0; c < 8; ++c) acc[r][c] = 0ULL;

    #pragma unroll 2
    for (int i = 0; i < HK; ++i) {
        ull af[8], wf[8];
        #pragma unroll
        for (int r = 0; r < 8; ++r) af[r] = As[(ty * 8 + r) * LDA + i];
        #pragma unroll
        for (int c = 0; c < 8; ++c) wf[c] = Ws[i * 128 + c * 16 + tx];
        #pragma unroll
        for (int r = 0; r < 8; ++r)
            #pragma unroll
            for (int c = 0; c < 8; ++c) acc[r][c] = ffma2(af[r], wf[c], acc[r][c]);
    }

    float bv[8];
    #pragma unroll
    for (int c = 0; c < 8; ++c) bv[c] = bih[nb * 128 + c * 16 + tx];
    #pragma unroll
    for (int r = 0; r < 8; ++r) {
        size_t m = (size_t)mb * 128 + ty * 8 + r;
        float* Crow = g_gx + m * NG3 + nb * 128 + tx;
        #pragma unroll
        for (int c = 0; c < 8; ++c)
            Crow[c * 16] = f32x2_sum(acc[r][c]) + bv[c];
    }
}

// ---------------- GRU scan: 128 CTAs x 2 batches, W_hh register-resident ----------------
__global__ __launch_bounds__(384, 1)
void gru_scan_kernel(const float* __restrict__ whh, const float* __restrict__ bhh) {
    __shared__ __align__(16) float h0s[NH];
    __shared__ __align__(16) float h1s[NH];
    __shared__ float accs[2 * NG3];          // [batch][row]

    int tid = threadIdx.x;                   // == W_hh row (g*128+j)
    int b0 = blockIdx.x * 2;

    // W_hh row -> 64 k-pair f32x2 registers
    ull wreg[64];
    {
        const float4* wp = reinterpret_cast<const float4*>(whh + (size_t)tid * NH);
        #pragma unroll
        for (int q = 0; q < 32; ++q) {
            float4 v = wp[q];
            wreg[2 * q]     = pack2(v.x, v.y);
            wreg[2 * q + 1] = pack2(v.z, v.w);
        }
    }
    float bias = bhh[tid];

    // update-thread state (tid < 256): ub = batch lane, uj = unit
    int ub = tid >> 7, uj = tid & 127;
    const float* gp   = g_gx   + ((size_t)(b0 + ub) * NT) * NG3 + uj;
    float*       hout = g_hseq + ((size_t)(b0 + ub) * NT) * NH  + uj;
    float gr = 0.f, gz = 0.f, gn = 0.f, hprev = 0.f;
    if (tid < 256) {
        if (ub == 0) h0s[uj] = 0.f; else h1s[uj] = 0.f;
        gr = gp[0]; gz = gp[128]; gn = gp[256];
    }
    __syncthreads();

    const ulonglong2* h0p = reinterpret_cast<const ulonglong2*>(h0s);
    const ulonglong2* h1p = reinterpret_cast<const ulonglong2*>(h1s);

    for (int t = 0; t < NT; ++t) {
        // matvec: all 384 threads, both batches in parallel f32x2 streams
        ull a0 = 0ULL, a1 = 0ULL;
        #pragma unroll
        for (int q = 0; q < 32; ++q) {
            ulonglong2 v0 = h0p[q];
            ulonglong2 v1 = h1p[q];
            a0 = ffma2(wreg[2 * q],     v0.x, a0);
            a0 = ffma2(wreg[2 * q + 1], v0.y, a0);
            a1 = ffma2(wreg[2 * q],     v1.x, a1);
            a1 = ffma2(wreg[2 * q + 1], v1.y, a1);
        }
        accs[tid]       = f32x2_sum(a0) + bias;
        accs[NG3 + tid] = f32x2_sum(a1) + bias;
        __syncthreads();

        if (tid < 256) {
            const float* ac = accs + ub * NG3;
            float r = sigf(gr + ac[uj]);
            float z = sigf(gz + ac[128 + uj]);
            float n = tanhf(gn + r * ac[256 + uj]);
            float hn = (1.0f - z) * n + z * hprev;
            hprev = hn;
            hout[(size_t)t * NH] = hn;
            if (ub == 0) h0s[uj] = hn; else h1s[uj] = hn;
            if (t + 1 < NT) {
                const float* g2 = gp + (size_t)(t + 1) * NG3;
                gr = g2[0]; gz = g2[128]; gn = g2[256];
            }
        }
        __syncthreads();
    }
}

// ---------------- final FC: out[b,c] = h_last[b,:] @ fc_w[c,:] + fc_b[c] ----------------
__global__ void fc_kernel(const float* __restrict__ fcw, const float* __restrict__ fcb,
                          float* __restrict__ out) {
    int b = blockIdx.x;
    int w = threadIdx.x >> 5;
    int lane = threadIdx.x & 31;
    if (w >= 6) return;
    const float* last = g_hseq + ((size_t)b * NT + NT - 1) * NH;
    float s = 0.f;
    #pragma unroll
    for (int k = 0; k < 4; ++k) {
        int j = lane + 32 * k;
        s += last[j] * fcw[w * NH + j];
    }
    #pragma unroll
    for (int o = 16; o; o >>= 1) s += __shfl_down_sync(0xffffffffu, s, o);
    if (lane == 0) out[b * 6 + w] = s + fcb[w];
}

// ---------------- launch ----------------
extern "C" void kernel_launch(void* const* d_in, const int* in_sizes, int n_in,
                              void* d_out, int out_size) {
    const float* x    = (const float*)d_in[0];
    const float* wih0 = (const float*)d_in[1];
    const float* wih1 = (const float*)d_in[2];
    const float* wih2 = (const float*)d_in[3];
    const float* whh  = (const float*)d_in[4];   // [3,384,128]
    const float* bih  = (const float*)d_in[5];   // [3,384]
    const float* bhh  = (const float*)d_in[6];   // [3,384]
    const float* fcw  = (const float*)d_in[7];
    const float* fcb  = (const float*)d_in[8];
    float* out = (float*)d_out;

    constexpr int SMEM64  = (128 * (64 / 2 + 2)  + (64 / 2)  * 128) * 8;   //  67584 B
    constexpr int SMEM128 = (128 * (128 / 2 + 2) + (128 / 2) * 128) * 8;   // 133120 B
    cudaFuncSetAttribute(gemm_gx_kernel<64>,  cudaFuncAttributeMaxDynamicSharedMemorySize, SMEM64);
    cudaFuncSetAttribute(gemm_gx_kernel<128>, cudaFuncAttributeMaxDynamicSharedMemorySize, SMEM128);

    dim3 ggrid(NB * NT / 128, NG3 / 128);

    float* g_hseq_ptr = nullptr;
    cudaGetSymbolAddress((void**)&g_hseq_ptr, g_hseq);

    // layer 0 (K = NIN = 64)
    pack_wih_kernel<<<(32 * NG3 + 255) / 256, 256>>>(wih0, 32);
    gemm_gx_kernel<64><<<ggrid, 256, SMEM64>>>(x, bih + 0 * NG3);
    gru_scan_kernel<<<NB / 2, 384>>>(whh + 0 * NG3 * NH, bhh + 0 * NG3);

    // layer 1 (K = NH = 128)
    pack_wih_kernel<<<(64 * NG3 + 255) / 256, 256>>>(wih1, 64);
    gemm_gx_kernel<128><<<ggrid, 256, SMEM128>>>(g_hseq_ptr, bih + 1 * NG3);
    gru_scan_kernel<<<NB / 2, 384>>>(whh + 1 * NG3 * NH, bhh + 1 * NG3);

    // layer 2 (K = NH = 128)
    pack_wih_kernel<<<(64 * NG3 + 255) / 256, 256>>>(wih2, 64);
    gemm_gx_kernel<128><<<ggrid, 256, SMEM128>>>(g_hseq_ptr, bih + 2 * NG3);
    gru_scan_kernel<<<NB / 2, 384>>>(whh + 2 * NG3 * NH, bhh + 2 * NG3);

    // final FC
    fc_kernel<<<NB, 192>>>(fcw, fcb, out);
}

// round 4
// speedup vs baseline: 1.2139x; 1.2139x over previous
#include <cuda_runtime.h>
#include <cuda_bf16.h>
#include <cstdint>

typedef unsigned long long ull;

#define NB 256
#define NT 512
#define NH 128
#define NG3 384

// ---------------- static scratch ----------------
__device__ float g_gx[(size_t)NB * NT * NG3];
__device__ float g_hseq[(size_t)NB * NT * NH];

// ---------------- helpers ----------------
__device__ __forceinline__ uint32_t smem_u32(const void* p) {
    uint32_t a;
    asm("{ .reg .u64 t; cvta.to.shared.u64 t, %1; cvt.u32.u64 %0, t; }" : "=r"(a) : "l"(p));
    return a;
}
// xor-swizzled byte offset for a [128][K] bf16 tile: 16B chunks permuted by row&7
__device__ __forceinline__ int swoff(int row, int k, int K) {
    return row * K * 2 + ((((k >> 3) ^ (row & 7)) << 4) | ((k & 7) << 1));
}
__device__ __forceinline__ uint32_t bf2_bits(float a, float b) {
    __nv_bfloat162 h = __floats2bfloat162_rn(a, b);
    return *reinterpret_cast<uint32_t*>(&h);
}
// f32x2 helpers (scan)
__device__ __forceinline__ ull ffma2(ull a, ull b, ull c) {
    ull d;
    asm("fma.rn.f32x2 %0, %1, %2, %3;" : "=l"(d) : "l"(a), "l"(b), "l"(c));
    return d;
}
__device__ __forceinline__ float f32x2_sum(ull a) {
    float lo, hi;
    asm("mov.b64 {%0, %1}, %2;" : "=f"(lo), "=f"(hi) : "l"(a));
    return lo + hi;
}
__device__ __forceinline__ ull pack2(float lo, float hi) {
    ull u;
    asm("mov.b64 %0, {%1, %2};" : "=l"(u) : "f"(lo), "f"(hi));
    return u;
}
__device__ __forceinline__ float sigf(float x) { return 1.0f / (1.0f + __expf(-x)); }

__device__ __forceinline__ void ldsm_x4(uint32_t* r, uint32_t addr) {
    asm volatile("ldmatrix.sync.aligned.m8n8.x4.shared.b16 {%0,%1,%2,%3}, [%4];"
                 : "=r"(r[0]), "=r"(r[1]), "=r"(r[2]), "=r"(r[3]) : "r"(addr));
}
__device__ __forceinline__ void ldsm_x2(uint32_t* r, uint32_t addr) {
    asm volatile("ldmatrix.sync.aligned.m8n8.x2.shared.b16 {%0,%1}, [%2];"
                 : "=r"(r[0]), "=r"(r[1]) : "r"(addr));
}
__device__ __forceinline__ void mma_bf16(float* c, const uint32_t* a, const uint32_t* b) {
    asm volatile(
        "mma.sync.aligned.m16n8k16.row.col.f32.bf16.bf16.f32 "
        "{%0,%1,%2,%3}, {%4,%5,%6,%7}, {%8,%9}, {%0,%1,%2,%3};"
        : "+f"(c[0]), "+f"(c[1]), "+f"(c[2]), "+f"(c[3])
        : "r"(a[0]), "r"(a[1]), "r"(a[2]), "r"(a[3]), "r"(b[0]), "r"(b[1]));
}

// ---------------- gx GEMM: g_gx[m,384] = A[m,K] @ W^T + b_ih ----------------
// 3-product split-bf16 emulation on mma.sync. CTA tile 128x128, full K in smem.
template <int K>
__global__ __launch_bounds__(256, 1)
void gemm_mma(const float* __restrict__ A, const float* __restrict__ W,
              const float* __restrict__ bih) {
    extern __shared__ char sm[];
    constexpr int TILE = 128 * K * 2;   // bytes per bf16 tile
    char* Ahi = sm;
    char* Alo = Ahi + TILE;
    char* Whi = Alo + TILE;
    char* Wlo = Whi + TILE;

    const int tid = threadIdx.x;
    const int wid = tid >> 5, lane = tid & 31;
    const int mb = blockIdx.x, nb = blockIdx.y;
    const int warp_m = wid >> 2;        // 0..1  (64 rows each)
    const int warp_n = wid & 3;         // 0..3  (32 cols each)

    // ---- load + split A tile ----
    {
        const float4* Ag = reinterpret_cast<const float4*>(A + (size_t)mb * 128 * K);
        #pragma unroll
        for (int p = 0; p < (128 * K / 4) / 256; ++p) {
            int idx = tid + p * 256;
            int m = idx / (K / 4);
            int k = (idx % (K / 4)) * 4;
            float4 v = Ag[idx];
            float h0 = __bfloat162float(__float2bfloat16(v.x));
            float h1 = __bfloat162float(__float2bfloat16(v.y));
            float h2 = __bfloat162float(__float2bfloat16(v.z));
            float h3 = __bfloat162float(__float2bfloat16(v.w));
            uint2 hi = make_uint2(bf2_bits(v.x, v.y), bf2_bits(v.z, v.w));
            uint2 lo = make_uint2(bf2_bits(v.x - h0, v.y - h1), bf2_bits(v.z - h2, v.w - h3));
            int sw = swoff(m, k, K);
            *reinterpret_cast<uint2*>(Ahi + sw) = hi;
            *reinterpret_cast<uint2*>(Alo + sw) = lo;
        }
    }
    // ---- load + split W tile (rows nb*128 .. +128 of [384][K]) ----
    {
        const float4* Wg = reinterpret_cast<const float4*>(W + (size_t)nb * 128 * K);
        #pragma unroll
        for (int p = 0; p < (128 * K / 4) / 256; ++p) {
            int idx = tid + p * 256;
            int n = idx / (K / 4);
            int k = (idx % (K / 4)) * 4;
            float4 v = Wg[idx];
            float h0 = __bfloat162float(__float2bfloat16(v.x));
            float h1 = __bfloat162float(__float2bfloat16(v.y));
            float h2 = __bfloat162float(__float2bfloat16(v.z));
            float h3 = __bfloat162float(__float2bfloat16(v.w));
            uint2 hi = make_uint2(bf2_bits(v.x, v.y), bf2_bits(v.z, v.w));
            uint2 lo = make_uint2(bf2_bits(v.x - h0, v.y - h1), bf2_bits(v.z - h2, v.w - h3));
            int sw = swoff(n, k, K);
            *reinterpret_cast<uint2*>(Whi + sw) = hi;
            *reinterpret_cast<uint2*>(Wlo + sw) = lo;
        }
    }
    __syncthreads();

    float acc[4][4][4];                 // [mf][nf][quad] fp32
    #pragma unroll
    for (int i = 0; i < 4; ++i)
        #pragma unroll
        for (int j = 0; j < 4; ++j)
            #pragma unroll
            for (int q = 0; q < 4; ++q) acc[i][j][q] = 0.f;

    const char* Abufs[3] = { Ahi, Alo, Ahi };   // (Ahi*Wlo)+(Alo*Whi)+(Ahi*Whi)
    const char* Wbufs[3] = { Wlo, Whi, Whi };

    #pragma unroll
    for (int s = 0; s < 3; ++s) {
        const char* Ab = Abufs[s];
        const char* Wb = Wbufs[s];
        #pragma unroll
        for (int kk = 0; kk < K / 16; ++kk) {
            const int kb = kk * 16;
            uint32_t af[4][4], bf[4][2];
            #pragma unroll
            for (int mf = 0; mf < 4; ++mf) {
                int row = warp_m * 64 + mf * 16 + (lane & 15);
                ldsm_x4(af[mf], smem_u32(Ab + swoff(row, kb + (lane >> 4) * 8, K)));
            }
            #pragma unroll
            for (int nf = 0; nf < 4; ++nf) {
                int rn = warp_n * 32 + nf * 8 + (lane & 7);
                ldsm_x2(bf[nf], smem_u32(Wb + swoff(rn, kb + ((lane >> 3) & 1) * 8, K)));
            }
            #pragma unroll
            for (int mf = 0; mf < 4; ++mf)
                #pragma unroll
                for (int nf = 0; nf < 4; ++nf)
                    mma_bf16(acc[mf][nf], af[mf], bf[nf]);
        }
    }

    // ---- epilogue: D + bias -> g_gx ----
    const int gr = lane >> 2, gc = (lane & 3) * 2;
    float bv[4][2];
    #pragma unroll
    for (int nf = 0; nf < 4; ++nf) {
        int col = nb * 128 + warp_n * 32 + nf * 8 + gc;
        bv[nf][0] = bih[col];
        bv[nf][1] = bih[col + 1];
    }
    #pragma unroll
    for (int mf = 0; mf < 4; ++mf) {
        int m0 = mb * 128 + warp_m * 64 + mf * 16 + gr;
        #pragma unroll
        for (int nf = 0; nf < 4; ++nf) {
            int col = nb * 128 + warp_n * 32 + nf * 8 + gc;
            float2 v0 = make_float2(acc[mf][nf][0] + bv[nf][0], acc[mf][nf][1] + bv[nf][1]);
            float2 v1 = make_float2(acc[mf][nf][2] + bv[nf][0], acc[mf][nf][3] + bv[nf][1]);
            *reinterpret_cast<float2*>(g_gx + (size_t)m0 * NG3 + col) = v0;
            *reinterpret_cast<float2*>(g_gx + (size_t)(m0 + 8) * NG3 + col) = v1;
        }
    }
}

// ---------------- GRU scan: 128 CTAs x 2 batches, W_hh register-resident ----------------
__global__ __launch_bounds__(384, 1)
void gru_scan_kernel(const float* __restrict__ whh, const float* __restrict__ bhh) {
    __shared__ __align__(16) float h0s[NH];
    __shared__ __align__(16) float h1s[NH];
    __shared__ float accs[2 * NG3];

    int tid = threadIdx.x;
    int b0 = blockIdx.x * 2;

    ull wreg[64];
    {
        const float4* wp = reinterpret_cast<const float4*>(whh + (size_t)tid * NH);
        #pragma unroll
        for (int q = 0; q < 32; ++q) {
            float4 v = wp[q];
            wreg[2 * q]     = pack2(v.x, v.y);
            wreg[2 * q + 1] = pack2(v.z, v.w);
        }
    }
    float bias = bhh[tid];

    int ub = tid >> 7, uj = tid & 127;
    const float* gp   = g_gx   + ((size_t)(b0 + ub) * NT) * NG3 + uj;
    float*       hout = g_hseq + ((size_t)(b0 + ub) * NT) * NH  + uj;
    float gr = 0.f, gz = 0.f, gn = 0.f, hprev = 0.f;
    if (tid < 256) {
        if (ub == 0) h0s[uj] = 0.f; else h1s[uj] = 0.f;
        gr = gp[0]; gz = gp[128]; gn = gp[256];
    }
    __syncthreads();

    const ulonglong2* h0p = reinterpret_cast<const ulonglong2*>(h0s);
    const ulonglong2* h1p = reinterpret_cast<const ulonglong2*>(h1s);

    for (int t = 0; t < NT; ++t) {
        ull a0 = 0ULL, a1 = 0ULL;
        #pragma unroll
        for (int q = 0; q < 32; ++q) {
            ulonglong2 v0 = h0p[q];
            ulonglong2 v1 = h1p[q];
            a0 = ffma2(wreg[2 * q],     v0.x, a0);
            a0 = ffma2(wreg[2 * q + 1], v0.y, a0);
            a1 = ffma2(wreg[2 * q],     v1.x, a1);
            a1 = ffma2(wreg[2 * q + 1], v1.y, a1);
        }
        accs[tid]       = f32x2_sum(a0) + bias;
        accs[NG3 + tid] = f32x2_sum(a1) + bias;
        __syncthreads();

        if (tid < 256) {
            const float* ac = accs + ub * NG3;
            float r = sigf(gr + ac[uj]);
            float z = sigf(gz + ac[128 + uj]);
            float n = tanhf(gn + r * ac[256 + uj]);
            float hn = (1.0f - z) * n + z * hprev;
            hprev = hn;
            hout[(size_t)t * NH] = hn;
            if (ub == 0) h0s[uj] = hn; else h1s[uj] = hn;
            if (t + 1 < NT) {
                const float* g2 = gp + (size_t)(t + 1) * NG3;
                gr = g2[0]; gz = g2[128]; gn = g2[256];
            }
        }
        __syncthreads();
    }
}

// ---------------- final FC ----------------
__global__ void fc_kernel(const float* __restrict__ fcw, const float* __restrict__ fcb,
                          float* __restrict__ out) {
    int b = blockIdx.x;
    int w = threadIdx.x >> 5;
    int lane = threadIdx.x & 31;
    if (w >= 6) return;
    const float* last = g_hseq + ((size_t)b * NT + NT - 1) * NH;
    float s = 0.f;
    #pragma unroll
    for (int k = 0; k < 4; ++k) {
        int j = lane + 32 * k;
        s += last[j] * fcw[w * NH + j];
    }
    #pragma unroll
    for (int o = 16; o; o >>= 1) s += __shfl_down_sync(0xffffffffu, s, o);
    if (lane == 0) out[b * 6 + w] = s + fcb[w];
}

// ---------------- launch ----------------
extern "C" void kernel_launch(void* const* d_in, const int* in_sizes, int n_in,
                              void* d_out, int out_size) {
    const float* x    = (const float*)d_in[0];
    const float* wih0 = (const float*)d_in[1];
    const float* wih1 = (const float*)d_in[2];
    const float* wih2 = (const float*)d_in[3];
    const float* whh  = (const float*)d_in[4];
    const float* bih  = (const float*)d_in[5];
    const float* bhh  = (const float*)d_in[6];
    const float* fcw  = (const float*)d_in[7];
    const float* fcb  = (const float*)d_in[8];
    float* out = (float*)d_out;

    constexpr int SMEM64  = 4 * 128 * 64 * 2;    //  65536
    constexpr int SMEM128 = 4 * 128 * 128 * 2;   // 131072
    cudaFuncSetAttribute(gemm_mma<64>,  cudaFuncAttributeMaxDynamicSharedMemorySize, SMEM64);
    cudaFuncSetAttribute(gemm_mma<128>, cudaFuncAttributeMaxDynamicSharedMemorySize, SMEM128);

    float* g_hseq_ptr = nullptr;
    cudaGetSymbolAddress((void**)&g_hseq_ptr, g_hseq);

    dim3 ggrid(NB * NT / 128, 3);

    gemm_mma<64><<<ggrid, 256, SMEM64>>>(x, wih0, bih + 0 * NG3);                 // 1
    gru_scan_kernel<<<NB / 2, 384>>>(whh + 0 * NG3 * NH, bhh + 0 * NG3);          // 2
    gemm_mma<128><<<ggrid, 256, SMEM128>>>(g_hseq_ptr, wih1, bih + 1 * NG3);      // 3
    gru_scan_kernel<<<NB / 2, 384>>>(whh + 1 * NG3 * NH, bhh + 1 * NG3);          // 4
    gemm_mma<128><<<ggrid, 256, SMEM128>>>(g_hseq_ptr, wih2, bih + 2 * NG3);      // 5
    gru_scan_kernel<<<NB / 2, 384>>>(whh + 2 * NG3 * NH, bhh + 2 * NG3);          // 6 (ncu -s 5 target)
    fc_kernel<<<NB, 192>>>(fcw, fcb, out);                                        // 7
}